// round 16
// baseline (speedup 1.0000x reference)
#include <cuda_runtime.h>
#include <cuda_fp16.h>
#include <cuda_bf16.h>

#define NN 20000
#define EE 320000
#define HH 8
#define DD 32
#define F1 128
#define HD 256   // H*D
#define TRB 64   // gemm row tile
#define NTILES 313           // ceil(NN/TRB)
#define SPLIT_T 156          // gemm2 chunk A tiles [0,156) = rows [0,9984)
#define SPLIT_N (SPLIT_T * TRB)

// ---------------- scratch (device globals; no allocation allowed) -------------
__device__ __half g_feat[NN * HD];     // [N, dim*8+head] fp16 features
__device__ float g_el[NN * HH];
__device__ float g_er[NN * HH];
__device__ float g_h[NN * DD];         // layer-1 output (fp32)
__device__ __half g_Wp1h[F1 * HD];     // permuted weights, n-major [col][k], fp16
__device__ __half g_Wp2h[DD * HD];
__device__ float g_alp1[HD], g_arp1[HD];
__device__ float g_alp2[HD], g_arp2[HD];
__device__ int   g_cnt[NN];            // INVARIANT: zero on entry to every call
__device__ int   g_rowptr[NN + 1];
__device__ int   g_fill[NN];
__device__ int   g_esrc[EE];

__device__ __forceinline__ void mma_f16(float& d0, float& d1, float& d2, float& d3,
                                        unsigned a0, unsigned a1, unsigned a2, unsigned a3,
                                        unsigned b0, unsigned b1) {
    asm volatile("mma.sync.aligned.m16n8k16.row.col.f32.f16.f16.f32 "
                 "{%0,%1,%2,%3}, {%4,%5,%6,%7}, {%8,%9}, {%0,%1,%2,%3};"
                 : "+f"(d0), "+f"(d1), "+f"(d2), "+f"(d3)
                 : "r"(a0), "r"(a1), "r"(a2), "r"(a3), "r"(b0), "r"(b1));
}

// ---------------- weight permutation + fp16 conversion (n-major output) -------
__global__ void perm_kernel(const float* __restrict__ W1,
                            const float* __restrict__ al1,
                            const float* __restrict__ ar1,
                            const float* __restrict__ W2,
                            const float* __restrict__ al2,
                            const float* __restrict__ ar2) {
    int t = blockIdx.x * 256 + threadIdx.x;
    if (t < F1 * HD) {
        int j = t / F1, k = t % F1;
        int L = ((j & 7) << 5) | (j >> 3);
        g_Wp1h[t] = __float2half_rn(W1[k * HD + L]);
    }
    if (t < DD * HD) {
        int j = t / DD, k = t % DD;
        int L = ((j & 7) << 5) | (j >> 3);
        g_Wp2h[t] = __float2half_rn(W2[k * HD + L]);
    }
    if (t < HD) {
        int L = ((t & 7) << 5) | (t >> 3);
        g_alp1[t] = al1[L]; g_arp1[t] = ar1[L];
        g_alp2[t] = al2[L]; g_arp2[t] = ar2[L];
    }
}

// ---------------- CSR chain (runs on forked stream) ---------------------------
__global__ void hist_kernel(const int* __restrict__ dst) {
    int e = blockIdx.x * blockDim.x + threadIdx.x;
    if (e < EE) atomicAdd(&g_cnt[dst[e]], 1);
}

__global__ void scan_kernel() {   // also restores g_cnt = 0 invariant
    __shared__ int ssum[1024];
    int t = threadIdx.x;
    const int chunk = (NN + 1023) / 1024;
    int b = t * chunk, e = min(b + chunk, NN);
    int s = 0;
    for (int i = b; i < e; i++) s += g_cnt[i];
    ssum[t] = s;
    __syncthreads();
    for (int off = 1; off < 1024; off <<= 1) {
        int v = (t >= off) ? ssum[t - off] : 0;
        __syncthreads();
        ssum[t] += v;
        __syncthreads();
    }
    int pref = (t > 0) ? ssum[t - 1] : 0;
    for (int i = b; i < e; i++) {
        int c = g_cnt[i];
        g_rowptr[i] = pref;
        g_fill[i]   = pref;
        g_cnt[i]    = 0;
        pref += c;
    }
    if (t == 1023) g_rowptr[NN] = ssum[1023];
}

__global__ void scatter_kernel(const int* __restrict__ src,
                               const int* __restrict__ dst) {
    int e = blockIdx.x * blockDim.x + threadIdx.x;
    if (e < EE) {
        int p = atomicAdd(&g_fill[dst[e]], 1);
        g_esrc[p] = src[e];
    }
}

// ---------------- fp16 tensor-core GEMM + fused el/er + fp16 feat -------------
// tile0: tile index offset (for chunked launches).
template <int K>
__global__ __launch_bounds__(256, 2) void gemm_tc_kernel(const float* __restrict__ X,
                                                         const __half* __restrict__ Wp,
                                                         const float* __restrict__ alp,
                                                         const float* __restrict__ arp,
                                                         int n, int tile0) {
    constexpr int KP = K + 8;               // half-row pad: stride ≡ 4 banks mod 32
    constexpr int STP = 260;                // fp32 stage row pad
    extern __shared__ float sh[];
    __half* Wsh = (__half*)sh;              // [HD][KP] n-major
    __half* Xsh = (__half*)sh + HD * KP;    // [TRB][KP] k contiguous
    int tid = threadIdx.x;
    int wid = tid >> 5, lane = tid & 31;
    int g = lane >> 2, tg = lane & 3;
    int warpM = wid >> 2, warpN = wid & 3;
    int nbase = warpN * 64;

    int r0 = (blockIdx.x + tile0) * TRB;
    int nr = min(TRB, n - r0);

    for (int idx = tid; idx < HD * (K / 2); idx += 256) {
        int j = idx / (K / 2), k2 = idx % (K / 2);
        *(__half2*)(Wsh + j * KP + 2 * k2) = *(const __half2*)(Wp + j * K + 2 * k2);
    }
    for (int idx = tid; idx < TRB * (K / 2); idx += 256) {
        int r = idx / (K / 2), c2 = idx % (K / 2);
        float2 xv = (r < nr) ? *(const float2*)(X + (size_t)(r0 + r) * K + 2 * c2)
                             : make_float2(0.f, 0.f);
        *(__half2*)(Xsh + r * KP + 2 * c2) = __float22half2_rn(xv);
    }
    __syncthreads();

    float acc[2][8][4];
#pragma unroll
    for (int m = 0; m < 2; m++)
#pragma unroll
        for (int t = 0; t < 8; t++)
#pragma unroll
            for (int c = 0; c < 4; c++) acc[m][t][c] = 0.f;

#pragma unroll
    for (int kk = 0; kk < K; kk += 16) {
        unsigned a[2][4];
#pragma unroll
        for (int m = 0; m < 2; m++) {
            int rb = warpM * 32 + m * 16;
            a[m][0] = *(const unsigned*)(Xsh + (rb + g) * KP + kk + 2 * tg);
            a[m][1] = *(const unsigned*)(Xsh + (rb + g + 8) * KP + kk + 2 * tg);
            a[m][2] = *(const unsigned*)(Xsh + (rb + g) * KP + kk + 2 * tg + 8);
            a[m][3] = *(const unsigned*)(Xsh + (rb + g + 8) * KP + kk + 2 * tg + 8);
        }
#pragma unroll
        for (int t = 0; t < 8; t++) {
            int ncol = nbase + t * 8 + g;
            unsigned b0 = *(const unsigned*)(Wsh + ncol * KP + kk + 2 * tg);
            unsigned b1 = *(const unsigned*)(Wsh + ncol * KP + kk + 2 * tg + 8);
            mma_f16(acc[0][t][0], acc[0][t][1], acc[0][t][2], acc[0][t][3],
                    a[0][0], a[0][1], a[0][2], a[0][3], b0, b1);
            mma_f16(acc[1][t][0], acc[1][t][1], acc[1][t][2], acc[1][t][3],
                    a[1][0], a[1][1], a[1][2], a[1][3], b0, b1);
        }
    }

    __syncthreads();
    float* stage = sh;          // [TRB][STP]
#pragma unroll
    for (int m = 0; m < 2; m++) {
        int rb = warpM * 32 + m * 16;
#pragma unroll
        for (int t = 0; t < 8; t++) {
            int c = nbase + t * 8 + 2 * tg;
            *(float2*)&stage[(rb + g) * STP + c] =
                make_float2(acc[m][t][0], acc[m][t][1]);
            *(float2*)&stage[(rb + g + 8) * STP + c] =
                make_float2(acc[m][t][2], acc[m][t][3]);
        }
    }
    __syncthreads();

    for (int i = tid; i < nr * 32; i += 256) {
        int row = i >> 5, cg = i & 31;
        const float4* s4 = (const float4*)&stage[row * STP + cg * 8];
        float4 f0 = s4[0], f1 = s4[1];
        __half2 h0 = __floats2half2_rn(f0.x, f0.y);
        __half2 h1 = __floats2half2_rn(f0.z, f0.w);
        __half2 h2 = __floats2half2_rn(f1.x, f1.y);
        __half2 h3 = __floats2half2_rn(f1.z, f1.w);
        uint4 u = make_uint4(*(unsigned*)&h0, *(unsigned*)&h1,
                             *(unsigned*)&h2, *(unsigned*)&h3);
        *(uint4*)(&g_feat[(size_t)(r0 + row) * HD + cg * 8]) = u;
    }

    float av[8], bv[8];
    {
        const float4* ap = (const float4*)(alp + lane * 8);
        const float4* bp = (const float4*)(arp + lane * 8);
        float4 a0 = ap[0], a1 = ap[1], b0 = bp[0], b1 = bp[1];
        av[0]=a0.x; av[1]=a0.y; av[2]=a0.z; av[3]=a0.w;
        av[4]=a1.x; av[5]=a1.y; av[6]=a1.z; av[7]=a1.w;
        bv[0]=b0.x; bv[1]=b0.y; bv[2]=b0.z; bv[3]=b0.w;
        bv[4]=b1.x; bv[5]=b1.y; bv[6]=b1.z; bv[7]=b1.w;
    }
    for (int row = wid; row < nr; row += 8) {
        const float4* f4 = (const float4*)(stage + row * STP + lane * 8);
        float4 f0 = f4[0], f1 = f4[1];
        float pa[8] = {f0.x*av[0], f0.y*av[1], f0.z*av[2], f0.w*av[3],
                       f1.x*av[4], f1.y*av[5], f1.z*av[6], f1.w*av[7]};
        float pb[8] = {f0.x*bv[0], f0.y*bv[1], f0.z*bv[2], f0.w*bv[3],
                       f1.x*bv[4], f1.y*bv[5], f1.z*bv[6], f1.w*bv[7]};
#pragma unroll
        for (int h = 0; h < 8; h++) {
#pragma unroll
            for (int off = 16; off; off >>= 1) {
                pa[h] += __shfl_xor_sync(0xffffffffu, pa[h], off);
                pb[h] += __shfl_xor_sync(0xffffffffu, pb[h], off);
            }
        }
        if (lane == 0) {
            float* elp = g_el + (size_t)(r0 + row) * HH;
            float* erp = g_er + (size_t)(r0 + row) * HH;
            *(float4*)(elp)     = make_float4(pa[0], pa[1], pa[2], pa[3]);
            *(float4*)(elp + 4) = make_float4(pa[4], pa[5], pa[6], pa[7]);
            *(float4*)(erp)     = make_float4(pb[0], pb[1], pb[2], pb[3]);
            *(float4*)(erp + 4) = make_float4(pb[4], pb[5], pb[6], pb[7]);
        }
    }
}

// ---------------- aggregation (R11 loop; node range [n0, n1)) ------------------
template <bool RELU_BEFORE_MEAN>
__global__ void agg_kernel(const float* __restrict__ bias,
                           float* __restrict__ out, int n0, int n1) {
    int node = n0 + blockIdx.x * (blockDim.x >> 5) + (threadIdx.x >> 5);
    if (node >= n1) return;
    int lane = threadIdx.x & 31;
    int hh = lane & 7;
    float er_l = g_er[node * HH + hh];
    int beg = g_rowptr[node], end = g_rowptr[node + 1];

    float acc[8];
#pragma unroll
    for (int h = 0; h < 8; h++) acc[h] = 0.f;
    float den_l = 0.f;

    int i = beg;
    for (; i + 4 <= end; i += 4) {
        int s0 = g_esrc[i + 0], s1 = g_esrc[i + 1];
        int s2 = g_esrc[i + 2], s3 = g_esrc[i + 3];
        float el0 = __ldg(g_el + s0 * HH + hh);
        float el1 = __ldg(g_el + s1 * HH + hh);
        float el2 = __ldg(g_el + s2 * HH + hh);
        float el3 = __ldg(g_el + s3 * HH + hh);
        uint4 u0 = *(const uint4*)(&g_feat[(size_t)s0 * HD + lane * 8]);
        uint4 u1 = *(const uint4*)(&g_feat[(size_t)s1 * HD + lane * 8]);
        uint4 u2 = *(const uint4*)(&g_feat[(size_t)s2 * HD + lane * 8]);
        uint4 u3 = *(const uint4*)(&g_feat[(size_t)s3 * HD + lane * 8]);
        float v0 = el0 + er_l; v0 = v0 > 0.f ? v0 : 0.2f * v0;
        float v1 = el1 + er_l; v1 = v1 > 0.f ? v1 : 0.2f * v1;
        float v2 = el2 + er_l; v2 = v2 > 0.f ? v2 : 0.2f * v2;
        float v3 = el3 + er_l; v3 = v3 > 0.f ? v3 : 0.2f * v3;
        float e0 = __expf(v0), e1 = __expf(v1);
        float e2 = __expf(v2), e3 = __expf(v3);
        den_l += (e0 + e1) + (e2 + e3);
        const unsigned* p0 = &u0.x;
        const unsigned* p1 = &u1.x;
        const unsigned* p2 = &u2.x;
        const unsigned* p3 = &u3.x;
#pragma unroll
        for (int q = 0; q < 4; q++) {       // q = head pair (2q, 2q+1)
            float2 f0 = __half22float2(*(const __half2*)&p0[q]);
            float2 f1 = __half22float2(*(const __half2*)&p1[q]);
            float2 f2 = __half22float2(*(const __half2*)&p2[q]);
            float2 f3 = __half22float2(*(const __half2*)&p3[q]);
            float wa0 = __shfl_sync(0xffffffffu, e0, 2 * q);
            float wa1 = __shfl_sync(0xffffffffu, e0, 2 * q + 1);
            float wb0 = __shfl_sync(0xffffffffu, e1, 2 * q);
            float wb1 = __shfl_sync(0xffffffffu, e1, 2 * q + 1);
            float wc0 = __shfl_sync(0xffffffffu, e2, 2 * q);
            float wc1 = __shfl_sync(0xffffffffu, e2, 2 * q + 1);
            float wd0 = __shfl_sync(0xffffffffu, e3, 2 * q);
            float wd1 = __shfl_sync(0xffffffffu, e3, 2 * q + 1);
            acc[2 * q]     = fmaf(wa0, f0.x, acc[2 * q]);
            acc[2 * q + 1] = fmaf(wa1, f0.y, acc[2 * q + 1]);
            acc[2 * q]     = fmaf(wb0, f1.x, acc[2 * q]);
            acc[2 * q + 1] = fmaf(wb1, f1.y, acc[2 * q + 1]);
            acc[2 * q]     = fmaf(wc0, f2.x, acc[2 * q]);
            acc[2 * q + 1] = fmaf(wc1, f2.y, acc[2 * q + 1]);
            acc[2 * q]     = fmaf(wd0, f3.x, acc[2 * q]);
            acc[2 * q + 1] = fmaf(wd1, f3.y, acc[2 * q + 1]);
        }
    }
    for (; i < end; i++) {
        int s = g_esrc[i];
        float elv = __ldg(g_el + s * HH + hh);
        uint4 u0 = *(const uint4*)(&g_feat[(size_t)s * HD + lane * 8]);
        float v = elv + er_l; v = v > 0.f ? v : 0.2f * v;
        float e = __expf(v);
        den_l += e;
        const unsigned* p0 = &u0.x;
#pragma unroll
        for (int q = 0; q < 4; q++) {
            float2 f0 = __half22float2(*(const __half2*)&p0[q]);
            float w0 = __shfl_sync(0xffffffffu, e, 2 * q);
            float w1 = __shfl_sync(0xffffffffu, e, 2 * q + 1);
            acc[2 * q]     = fmaf(w0, f0.x, acc[2 * q]);
            acc[2 * q + 1] = fmaf(w1, f0.y, acc[2 * q + 1]);
        }
    }

    float sum = 0.f;
#pragma unroll
    for (int h = 0; h < 8; h++) {
        float dh = __shfl_sync(0xffffffffu, den_l, h);
        float r = (dh > 0.f) ? __fdividef(acc[h], dh) : 0.f;
        r += bias[h * DD + lane];
        if (RELU_BEFORE_MEAN) r = fmaxf(r, 0.f);
        sum += r;
    }
    out[node * DD + lane] = sum * 0.125f;
}

// ---------------- stream/event resources (created once, pre-capture) ----------
struct HxRes {
    cudaStream_t s2;
    cudaEvent_t e0, e1, e2, eB;
    HxRes() {
        cudaStreamCreateWithFlags(&s2, cudaStreamNonBlocking);
        cudaEventCreateWithFlags(&e0, cudaEventDisableTiming);
        cudaEventCreateWithFlags(&e1, cudaEventDisableTiming);
        cudaEventCreateWithFlags(&e2, cudaEventDisableTiming);
        cudaEventCreateWithFlags(&eB, cudaEventDisableTiming);
    }
};
static HxRes& hx() { static HxRes r; return r; }

// ---------------- launcher -----------------------------------------------------
extern "C" void kernel_launch(void* const* d_in, const int* in_sizes, int n_in,
                              void* d_out, int out_size) {
    const float* x   = (const float*)d_in[0];
    const int*   src = (const int*)d_in[1];
    const int*   dst = (const int*)d_in[2];
    const float* W1  = (const float*)d_in[3];
    const float* al1 = (const float*)d_in[4];
    const float* ar1 = (const float*)d_in[5];
    const float* b1  = (const float*)d_in[6];
    const float* W2  = (const float*)d_in[7];
    const float* al2 = (const float*)d_in[8];
    const float* ar2 = (const float*)d_in[9];
    const float* b2  = (const float*)d_in[10];
    float* out = (float*)d_out;

    float *hbuf, *alp1, *arp1, *alp2, *arp2;
    __half *Wp1, *Wp2;
    cudaGetSymbolAddress((void**)&hbuf, g_h);
    cudaGetSymbolAddress((void**)&Wp1, g_Wp1h);
    cudaGetSymbolAddress((void**)&Wp2, g_Wp2h);
    cudaGetSymbolAddress((void**)&alp1, g_alp1);
    cudaGetSymbolAddress((void**)&arp1, g_arp1);
    cudaGetSymbolAddress((void**)&alp2, g_alp2);
    cudaGetSymbolAddress((void**)&arp2, g_arp2);

    constexpr int smem1 = (HD * (F1 + 8) + TRB * (F1 + 8)) * 2;
    constexpr int smem2 = TRB * 260 * 4;
    cudaFuncSetAttribute(gemm_tc_kernel<F1>,
                         cudaFuncAttributeMaxDynamicSharedMemorySize, smem1);
    cudaFuncSetAttribute(gemm_tc_kernel<DD>,
                         cudaFuncAttributeMaxDynamicSharedMemorySize, smem2);

    HxRes& R = hx();

    // fork: CSR chain on s2, overlapped with perm + gemm1
    cudaEventRecord(R.e0, 0);
    cudaStreamWaitEvent(R.s2, R.e0, 0);
    hist_kernel<<<(EE + 255) / 256, 256, 0, R.s2>>>(dst);
    scan_kernel<<<1, 1024, 0, R.s2>>>();
    scatter_kernel<<<(EE + 255) / 256, 256, 0, R.s2>>>(src, dst);
    cudaEventRecord(R.e1, R.s2);

    // main stream: perm, then layer-1 GEMM (+fused el/er, fp16 feat)
    perm_kernel<<<(F1 * HD + 255) / 256, 256>>>(W1, al1, ar1, W2, al2, ar2);
    gemm_tc_kernel<F1><<<NTILES, 256, smem1>>>(x, Wp1, alp1, arp1, NN, 0);
    cudaEventRecord(R.e2, 0);

    // pipeline: agg1_A on main; agg1_B on s2 (needs CSR [in-order] + gemm1 [e2])
    cudaStreamWaitEvent(0, R.e1, 0);
    cudaStreamWaitEvent(R.s2, R.e2, 0);
    agg_kernel<true><<<SPLIT_N / 8, 256>>>(b1, hbuf, 0, SPLIT_N);
    agg_kernel<true><<<(NN - SPLIT_N + 7) / 8, 256, 0, R.s2>>>(b1, hbuf, SPLIT_N, NN);
    cudaEventRecord(R.eB, R.s2);

    // gemm2 chunk A (rows [0, SPLIT_N)) overlaps agg1_B; chunk B after eB
    gemm_tc_kernel<DD><<<SPLIT_T, 256, smem2>>>(hbuf, Wp2, alp2, arp2, NN, 0);
    cudaStreamWaitEvent(0, R.eB, 0);
    gemm_tc_kernel<DD><<<NTILES - SPLIT_T, 256, smem2>>>(hbuf, Wp2, alp2, arp2, NN, SPLIT_T);

    // final aggregation
    agg_kernel<false><<<(NN + 7) / 8, 256>>>(b2, out, 0, NN);
}

// round 17
// speedup vs baseline: 1.0831x; 1.0831x over previous
#include <cuda_runtime.h>
#include <cuda_fp16.h>
#include <cuda_bf16.h>

#define NN 20000
#define EE 320000
#define HH 8
#define DD 32
#define F1 128
#define HD 256   // H*D
#define TRB 64   // gemm row tile

// ---------------- scratch (device globals; no allocation allowed) -------------
__device__ __half g_feat[NN * HD];     // [N, dim*8+head] fp16 features
__device__ float g_el[NN * HH];
__device__ float g_er[NN * HH];
__device__ float g_h[NN * DD];         // layer-1 output (fp32)
__device__ __half g_Wp1h[F1 * HD];     // permuted weights, n-major [col][k], fp16
__device__ __half g_Wp2h[DD * HD];
__device__ float g_alp1[HD], g_arp1[HD];
__device__ float g_alp2[HD], g_arp2[HD];
__device__ int   g_cnt[NN];            // INVARIANT: zero on entry to every call
__device__ int   g_rowptr[NN + 1];
__device__ int   g_fill[NN];
__device__ int   g_esrc[EE];

__device__ __forceinline__ void mma_f16(float& d0, float& d1, float& d2, float& d3,
                                        unsigned a0, unsigned a1, unsigned a2, unsigned a3,
                                        unsigned b0, unsigned b1) {
    asm volatile("mma.sync.aligned.m16n8k16.row.col.f32.f16.f16.f32 "
                 "{%0,%1,%2,%3}, {%4,%5,%6,%7}, {%8,%9}, {%0,%1,%2,%3};"
                 : "+f"(d0), "+f"(d1), "+f"(d2), "+f"(d3)
                 : "r"(a0), "r"(a1), "r"(a2), "r"(a3), "r"(b0), "r"(b1));
}

// ---------------- weight permutation + fp16 conversion (n-major output) -------
__global__ void perm_kernel(const float* __restrict__ W1,
                            const float* __restrict__ al1,
                            const float* __restrict__ ar1,
                            const float* __restrict__ W2,
                            const float* __restrict__ al2,
                            const float* __restrict__ ar2) {
    int t = blockIdx.x * 256 + threadIdx.x;
    if (t < F1 * HD) {
        int j = t / F1, k = t % F1;
        int L = ((j & 7) << 5) | (j >> 3);
        g_Wp1h[t] = __float2half_rn(W1[k * HD + L]);
    }
    if (t < DD * HD) {
        int j = t / DD, k = t % DD;
        int L = ((j & 7) << 5) | (j >> 3);
        g_Wp2h[t] = __float2half_rn(W2[k * HD + L]);
    }
    if (t < HD) {
        int L = ((t & 7) << 5) | (t >> 3);
        g_alp1[t] = al1[L]; g_arp1[t] = ar1[L];
        g_alp2[t] = al2[L]; g_arp2[t] = ar2[L];
    }
}

// ---------------- CSR chain (runs on forked stream) ---------------------------
__global__ void hist_kernel(const int* __restrict__ dst) {
    int e = blockIdx.x * blockDim.x + threadIdx.x;
    if (e < EE) atomicAdd(&g_cnt[dst[e]], 1);
}

__global__ void scan_kernel() {   // also restores g_cnt = 0 invariant
    __shared__ int ssum[1024];
    int t = threadIdx.x;
    const int chunk = (NN + 1023) / 1024;
    int b = t * chunk, e = min(b + chunk, NN);
    int s = 0;
    for (int i = b; i < e; i++) s += g_cnt[i];
    ssum[t] = s;
    __syncthreads();
    for (int off = 1; off < 1024; off <<= 1) {
        int v = (t >= off) ? ssum[t - off] : 0;
        __syncthreads();
        ssum[t] += v;
        __syncthreads();
    }
    int pref = (t > 0) ? ssum[t - 1] : 0;
    for (int i = b; i < e; i++) {
        int c = g_cnt[i];
        g_rowptr[i] = pref;
        g_fill[i]   = pref;
        g_cnt[i]    = 0;
        pref += c;
    }
    if (t == 1023) g_rowptr[NN] = ssum[1023];
}

__global__ void scatter_kernel(const int* __restrict__ src,
                               const int* __restrict__ dst) {
    int e = blockIdx.x * blockDim.x + threadIdx.x;
    if (e < EE) {
        int p = atomicAdd(&g_fill[dst[e]], 1);
        g_esrc[p] = src[e];
    }
}

// ---------------- fp16 tensor-core GEMM + fused el/er + fp16 feat -------------
template <int K>
__global__ __launch_bounds__(256, 2) void gemm_tc_kernel(const float* __restrict__ X,
                                                         const __half* __restrict__ Wp,
                                                         const float* __restrict__ alp,
                                                         const float* __restrict__ arp,
                                                         int n) {
    constexpr int KP = K + 8;               // half-row pad: stride ≡ 4 banks mod 32
    constexpr int STP = 260;                // fp32 stage row pad
    extern __shared__ float sh[];
    __half* Wsh = (__half*)sh;              // [HD][KP] n-major
    __half* Xsh = (__half*)sh + HD * KP;    // [TRB][KP] k contiguous
    int tid = threadIdx.x;
    int wid = tid >> 5, lane = tid & 31;
    int g = lane >> 2, tg = lane & 3;
    int warpM = wid >> 2, warpN = wid & 3;
    int nbase = warpN * 64;

    int r0 = blockIdx.x * TRB;
    int nr = min(TRB, n - r0);

    for (int idx = tid; idx < HD * (K / 2); idx += 256) {
        int j = idx / (K / 2), k2 = idx % (K / 2);
        *(__half2*)(Wsh + j * KP + 2 * k2) = *(const __half2*)(Wp + j * K + 2 * k2);
    }
    for (int idx = tid; idx < TRB * (K / 2); idx += 256) {
        int r = idx / (K / 2), c2 = idx % (K / 2);
        float2 xv = (r < nr) ? *(const float2*)(X + (size_t)(r0 + r) * K + 2 * c2)
                             : make_float2(0.f, 0.f);
        *(__half2*)(Xsh + r * KP + 2 * c2) = __float22half2_rn(xv);
    }
    __syncthreads();

    float acc[2][8][4];
#pragma unroll
    for (int m = 0; m < 2; m++)
#pragma unroll
        for (int t = 0; t < 8; t++)
#pragma unroll
            for (int c = 0; c < 4; c++) acc[m][t][c] = 0.f;

#pragma unroll
    for (int kk = 0; kk < K; kk += 16) {
        unsigned a[2][4];
#pragma unroll
        for (int m = 0; m < 2; m++) {
            int rb = warpM * 32 + m * 16;
            a[m][0] = *(const unsigned*)(Xsh + (rb + g) * KP + kk + 2 * tg);
            a[m][1] = *(const unsigned*)(Xsh + (rb + g + 8) * KP + kk + 2 * tg);
            a[m][2] = *(const unsigned*)(Xsh + (rb + g) * KP + kk + 2 * tg + 8);
            a[m][3] = *(const unsigned*)(Xsh + (rb + g + 8) * KP + kk + 2 * tg + 8);
        }
#pragma unroll
        for (int t = 0; t < 8; t++) {
            int ncol = nbase + t * 8 + g;
            unsigned b0 = *(const unsigned*)(Wsh + ncol * KP + kk + 2 * tg);
            unsigned b1 = *(const unsigned*)(Wsh + ncol * KP + kk + 2 * tg + 8);
            mma_f16(acc[0][t][0], acc[0][t][1], acc[0][t][2], acc[0][t][3],
                    a[0][0], a[0][1], a[0][2], a[0][3], b0, b1);
            mma_f16(acc[1][t][0], acc[1][t][1], acc[1][t][2], acc[1][t][3],
                    a[1][0], a[1][1], a[1][2], a[1][3], b0, b1);
        }
    }

    __syncthreads();
    float* stage = sh;          // [TRB][STP]
#pragma unroll
    for (int m = 0; m < 2; m++) {
        int rb = warpM * 32 + m * 16;
#pragma unroll
        for (int t = 0; t < 8; t++) {
            int c = nbase + t * 8 + 2 * tg;
            *(float2*)&stage[(rb + g) * STP + c] =
                make_float2(acc[m][t][0], acc[m][t][1]);
            *(float2*)&stage[(rb + g + 8) * STP + c] =
                make_float2(acc[m][t][2], acc[m][t][3]);
        }
    }
    __syncthreads();

    for (int i = tid; i < nr * 32; i += 256) {
        int row = i >> 5, cg = i & 31;
        const float4* s4 = (const float4*)&stage[row * STP + cg * 8];
        float4 f0 = s4[0], f1 = s4[1];
        __half2 h0 = __floats2half2_rn(f0.x, f0.y);
        __half2 h1 = __floats2half2_rn(f0.z, f0.w);
        __half2 h2 = __floats2half2_rn(f1.x, f1.y);
        __half2 h3 = __floats2half2_rn(f1.z, f1.w);
        uint4 u = make_uint4(*(unsigned*)&h0, *(unsigned*)&h1,
                             *(unsigned*)&h2, *(unsigned*)&h3);
        *(uint4*)(&g_feat[(size_t)(r0 + row) * HD + cg * 8]) = u;
    }

    float av[8], bv[8];
    {
        const float4* ap = (const float4*)(alp + lane * 8);
        const float4* bp = (const float4*)(arp + lane * 8);
        float4 a0 = ap[0], a1 = ap[1], b0 = bp[0], b1 = bp[1];
        av[0]=a0.x; av[1]=a0.y; av[2]=a0.z; av[3]=a0.w;
        av[4]=a1.x; av[5]=a1.y; av[6]=a1.z; av[7]=a1.w;
        bv[0]=b0.x; bv[1]=b0.y; bv[2]=b0.z; bv[3]=b0.w;
        bv[4]=b1.x; bv[5]=b1.y; bv[6]=b1.z; bv[7]=b1.w;
    }
    for (int row = wid; row < nr; row += 8) {
        const float4* f4 = (const float4*)(stage + row * STP + lane * 8);
        float4 f0 = f4[0], f1 = f4[1];
        float pa[8] = {f0.x*av[0], f0.y*av[1], f0.z*av[2], f0.w*av[3],
                       f1.x*av[4], f1.y*av[5], f1.z*av[6], f1.w*av[7]};
        float pb[8] = {f0.x*bv[0], f0.y*bv[1], f0.z*bv[2], f0.w*bv[3],
                       f1.x*bv[4], f1.y*bv[5], f1.z*bv[6], f1.w*bv[7]};
#pragma unroll
        for (int h = 0; h < 8; h++) {
#pragma unroll
            for (int off = 16; off; off >>= 1) {
                pa[h] += __shfl_xor_sync(0xffffffffu, pa[h], off);
                pb[h] += __shfl_xor_sync(0xffffffffu, pb[h], off);
            }
        }
        if (lane == 0) {
            float* elp = g_el + (size_t)(r0 + row) * HH;
            float* erp = g_er + (size_t)(r0 + row) * HH;
            *(float4*)(elp)     = make_float4(pa[0], pa[1], pa[2], pa[3]);
            *(float4*)(elp + 4) = make_float4(pa[4], pa[5], pa[6], pa[7]);
            *(float4*)(erp)     = make_float4(pb[0], pb[1], pb[2], pb[3]);
            *(float4*)(erp + 4) = make_float4(pb[4], pb[5], pb[6], pb[7]);
        }
    }
}

// ---------------- aggregation (R11 loop: 4-deep named-scalar batch) -----------
template <bool RELU_BEFORE_MEAN>
__global__ void agg_kernel(const float* __restrict__ bias,
                           float* __restrict__ out) {
    int node = blockIdx.x * (blockDim.x >> 5) + (threadIdx.x >> 5);
    if (node >= NN) return;
    int lane = threadIdx.x & 31;
    int hh = lane & 7;
    float er_l = g_er[node * HH + hh];
    int beg = g_rowptr[node], end = g_rowptr[node + 1];

    float acc[8];
#pragma unroll
    for (int h = 0; h < 8; h++) acc[h] = 0.f;
    float den_l = 0.f;

    int i = beg;
    for (; i + 4 <= end; i += 4) {
        int s0 = g_esrc[i + 0], s1 = g_esrc[i + 1];
        int s2 = g_esrc[i + 2], s3 = g_esrc[i + 3];
        float el0 = __ldg(g_el + s0 * HH + hh);
        float el1 = __ldg(g_el + s1 * HH + hh);
        float el2 = __ldg(g_el + s2 * HH + hh);
        float el3 = __ldg(g_el + s3 * HH + hh);
        uint4 u0 = *(const uint4*)(&g_feat[(size_t)s0 * HD + lane * 8]);
        uint4 u1 = *(const uint4*)(&g_feat[(size_t)s1 * HD + lane * 8]);
        uint4 u2 = *(const uint4*)(&g_feat[(size_t)s2 * HD + lane * 8]);
        uint4 u3 = *(const uint4*)(&g_feat[(size_t)s3 * HD + lane * 8]);
        float v0 = el0 + er_l; v0 = v0 > 0.f ? v0 : 0.2f * v0;
        float v1 = el1 + er_l; v1 = v1 > 0.f ? v1 : 0.2f * v1;
        float v2 = el2 + er_l; v2 = v2 > 0.f ? v2 : 0.2f * v2;
        float v3 = el3 + er_l; v3 = v3 > 0.f ? v3 : 0.2f * v3;
        float e0 = __expf(v0), e1 = __expf(v1);
        float e2 = __expf(v2), e3 = __expf(v3);
        den_l += (e0 + e1) + (e2 + e3);
        const unsigned* p0 = &u0.x;
        const unsigned* p1 = &u1.x;
        const unsigned* p2 = &u2.x;
        const unsigned* p3 = &u3.x;
#pragma unroll
        for (int q = 0; q < 4; q++) {       // q = head pair (2q, 2q+1)
            float2 f0 = __half22float2(*(const __half2*)&p0[q]);
            float2 f1 = __half22float2(*(const __half2*)&p1[q]);
            float2 f2 = __half22float2(*(const __half2*)&p2[q]);
            float2 f3 = __half22float2(*(const __half2*)&p3[q]);
            float wa0 = __shfl_sync(0xffffffffu, e0, 2 * q);
            float wa1 = __shfl_sync(0xffffffffu, e0, 2 * q + 1);
            float wb0 = __shfl_sync(0xffffffffu, e1, 2 * q);
            float wb1 = __shfl_sync(0xffffffffu, e1, 2 * q + 1);
            float wc0 = __shfl_sync(0xffffffffu, e2, 2 * q);
            float wc1 = __shfl_sync(0xffffffffu, e2, 2 * q + 1);
            float wd0 = __shfl_sync(0xffffffffu, e3, 2 * q);
            float wd1 = __shfl_sync(0xffffffffu, e3, 2 * q + 1);
            acc[2 * q]     = fmaf(wa0, f0.x, acc[2 * q]);
            acc[2 * q + 1] = fmaf(wa1, f0.y, acc[2 * q + 1]);
            acc[2 * q]     = fmaf(wb0, f1.x, acc[2 * q]);
            acc[2 * q + 1] = fmaf(wb1, f1.y, acc[2 * q + 1]);
            acc[2 * q]     = fmaf(wc0, f2.x, acc[2 * q]);
            acc[2 * q + 1] = fmaf(wc1, f2.y, acc[2 * q + 1]);
            acc[2 * q]     = fmaf(wd0, f3.x, acc[2 * q]);
            acc[2 * q + 1] = fmaf(wd1, f3.y, acc[2 * q + 1]);
        }
    }
    for (; i < end; i++) {
        int s = g_esrc[i];
        float elv = __ldg(g_el + s * HH + hh);
        uint4 u0 = *(const uint4*)(&g_feat[(size_t)s * HD + lane * 8]);
        float v = elv + er_l; v = v > 0.f ? v : 0.2f * v;
        float e = __expf(v);
        den_l += e;
        const unsigned* p0 = &u0.x;
#pragma unroll
        for (int q = 0; q < 4; q++) {
            float2 f0 = __half22float2(*(const __half2*)&p0[q]);
            float w0 = __shfl_sync(0xffffffffu, e, 2 * q);
            float w1 = __shfl_sync(0xffffffffu, e, 2 * q + 1);
            acc[2 * q]     = fmaf(w0, f0.x, acc[2 * q]);
            acc[2 * q + 1] = fmaf(w1, f0.y, acc[2 * q + 1]);
        }
    }

    float sum = 0.f;
#pragma unroll
    for (int h = 0; h < 8; h++) {
        float dh = __shfl_sync(0xffffffffu, den_l, h);
        float r = (dh > 0.f) ? __fdividef(acc[h], dh) : 0.f;
        r += bias[h * DD + lane];
        if (RELU_BEFORE_MEAN) r = fmaxf(r, 0.f);
        sum += r;
    }
    out[node * DD + lane] = sum * 0.125f;
}

// ---------------- stream/event resources (created once, pre-capture) ----------
struct HxRes {
    cudaStream_t s2;
    cudaEvent_t e0, e1;
    HxRes() {
        cudaStreamCreateWithFlags(&s2, cudaStreamNonBlocking);
        cudaEventCreateWithFlags(&e0, cudaEventDisableTiming);
        cudaEventCreateWithFlags(&e1, cudaEventDisableTiming);
    }
};
static HxRes& hx() { static HxRes r; return r; }

// ---------------- launcher -----------------------------------------------------
extern "C" void kernel_launch(void* const* d_in, const int* in_sizes, int n_in,
                              void* d_out, int out_size) {
    const float* x   = (const float*)d_in[0];
    const int*   src = (const int*)d_in[1];
    const int*   dst = (const int*)d_in[2];
    const float* W1  = (const float*)d_in[3];
    const float* al1 = (const float*)d_in[4];
    const float* ar1 = (const float*)d_in[5];
    const float* b1  = (const float*)d_in[6];
    const float* W2  = (const float*)d_in[7];
    const float* al2 = (const float*)d_in[8];
    const float* ar2 = (const float*)d_in[9];
    const float* b2  = (const float*)d_in[10];
    float* out = (float*)d_out;

    float *hbuf, *alp1, *arp1, *alp2, *arp2;
    __half *Wp1, *Wp2;
    cudaGetSymbolAddress((void**)&hbuf, g_h);
    cudaGetSymbolAddress((void**)&Wp1, g_Wp1h);
    cudaGetSymbolAddress((void**)&Wp2, g_Wp2h);
    cudaGetSymbolAddress((void**)&alp1, g_alp1);
    cudaGetSymbolAddress((void**)&arp1, g_arp1);
    cudaGetSymbolAddress((void**)&alp2, g_alp2);
    cudaGetSymbolAddress((void**)&arp2, g_arp2);

    const int NTB = (NN + TRB - 1) / TRB;  // 313 tiles
    constexpr int smem1 = (HD * (F1 + 8) + TRB * (F1 + 8)) * 2;
    constexpr int smem2 = TRB * 260 * 4;
    cudaFuncSetAttribute(gemm_tc_kernel<F1>,
                         cudaFuncAttributeMaxDynamicSharedMemorySize, smem1);
    cudaFuncSetAttribute(gemm_tc_kernel<DD>,
                         cudaFuncAttributeMaxDynamicSharedMemorySize, smem2);

    HxRes& R = hx();

    // fork: CSR prefix (hist, scan) on s2
    cudaEventRecord(R.e0, 0);
    cudaStreamWaitEvent(R.s2, R.e0, 0);
    hist_kernel<<<(EE + 255) / 256, 256, 0, R.s2>>>(dst);             // sub #1
    scan_kernel<<<1, 1024, 0, R.s2>>>();                              // sub #2

    // main stream: perm, then layer-1 GEMM (+fused el/er, fp16 feat)
    perm_kernel<<<(F1 * HD + 255) / 256, 256>>>(W1, al1, ar1, W2, al2, ar2); // #3
    gemm_tc_kernel<F1><<<NTB, 256, smem1>>>(x, Wp1, alp1, arp1, NN);  // sub #4 (ncu target)

    // scatter continues the CSR chain on s2 (in-order after scan), runs ∥ gemm1
    scatter_kernel<<<(EE + 255) / 256, 256, 0, R.s2>>>(src, dst);     // sub #5
    cudaEventRecord(R.e1, R.s2);

    // join, then aggregate layer 1
    cudaStreamWaitEvent(0, R.e1, 0);
    agg_kernel<true><<<(NN + 7) / 8, 256>>>(b1, hbuf);                // sub #6

    // layer 2
    gemm_tc_kernel<DD><<<NTB, 256, smem2>>>(hbuf, Wp2, alp2, arp2, NN);
    agg_kernel<false><<<(NN + 7) / 8, 256>>>(b2, out);
}